// round 13
// baseline (speedup 1.0000x reference)
#include <cuda_runtime.h>
#include <cuda_bf16.h>
#include <cuda_fp16.h>
#include <math.h>

#define N_NODES 100000
#define N_EDGES 20000
#define N_INC   800000
#define D_IN    256
#define D_HID   16
#define D_OUT   40
#define PAD_E   128
#define PAD_V   64

// ---------------- scratch (device globals) ----------------
__device__ __half2 g_XW1h[(size_t)N_NODES * (D_HID / 2)]; // H@W1, fp16, 32B rows
__device__ __half2 g_e1h [(size_t)N_EDGES * (D_HID / 2)]; // e_feat1, fp16, 32B rows
__device__ __half2 g_X2h [(size_t)N_NODES * (D_HID / 2)]; // x=relu(...), fp16, 32B rows
__device__ __half2 g_e2h [(size_t)N_EDGES * (D_HID / 2)]; // e_feat2, fp16, 32B rows
__device__ int     g_cnt_e[N_EDGES];   // zero-init; re-zeroed by ng2 each call
__device__ int     g_cnt_v[N_NODES];   // zero-init; re-zeroed by ng2 each call
__device__ unsigned g_buf_e[(size_t)N_EDGES * PAD_E];     // packed (v<<15)|q, q=round(w*32767)
__device__ int     g_buf_v[(size_t)N_NODES * PAD_V];      // edge idx

#define WQ_SCALE (1.f / 32767.f)
__device__ __forceinline__ void unpack_vw(unsigned p, int& v, float& wv) {
    v = (int)(p >> 15);
    wv = (float)(p & 0x7FFFu) * WQ_SCALE;
}

// ---------------- GEMM1 + bucket fill (merged; disjoint block ranges) --------
#define GEMM1_BLOCKS ((N_NODES + 255) / 256)
#define FILL_BLOCKS  ((N_INC + 255) / 256)
__global__ void gemm1_fill_kernel(const float* __restrict__ H, const float* __restrict__ W1,
                                  const int* __restrict__ ni, const int* __restrict__ ei,
                                  const float* __restrict__ w) {
    if (blockIdx.x >= GEMM1_BLOCKS) {
        int i = (blockIdx.x - GEMM1_BLOCKS) * blockDim.x + threadIdx.x;
        if (i >= N_INC) return;
        int v = __ldg(&ni[i]);
        int e = __ldg(&ei[i]);
        float wv = __ldg(&w[v]);
        unsigned q = (unsigned)__float2int_rn(wv * 32767.f);
        int se = atomicAdd(&g_cnt_e[e], 1);
        if (se < PAD_E) g_buf_e[(size_t)e * PAD_E + se] = ((unsigned)v << 15) | q;
        int sv = atomicAdd(&g_cnt_v[v], 1);
        if (sv < PAD_V) g_buf_v[(size_t)v * PAD_V + sv] = e;
        return;
    }
    __shared__ float sW[D_IN * D_HID];
    for (int i = threadIdx.x; i < D_IN * D_HID; i += blockDim.x) sW[i] = W1[i];
    __syncthreads();

    int row = blockIdx.x * blockDim.x + threadIdx.x;
    if (row >= N_NODES) return;

    float acc[D_HID];
#pragma unroll
    for (int j = 0; j < D_HID; j++) acc[j] = 0.f;

    const float4* hp = reinterpret_cast<const float4*>(H + (size_t)row * D_IN);
#pragma unroll 4
    for (int k4 = 0; k4 < D_IN / 4; k4++) {
        float4 hv = __ldcs(&hp[k4]);
        const float* wr = &sW[k4 * 4 * D_HID];
        float xs[4] = {hv.x, hv.y, hv.z, hv.w};
#pragma unroll
        for (int c = 0; c < 4; c++) {
            const float4* w4 = reinterpret_cast<const float4*>(wr + c * D_HID);
            float4 wa = w4[0], wb = w4[1], wc = w4[2], wd = w4[3];
            float x = xs[c];
            acc[0]  += x * wa.x;  acc[1]  += x * wa.y;  acc[2]  += x * wa.z;  acc[3]  += x * wa.w;
            acc[4]  += x * wb.x;  acc[5]  += x * wb.y;  acc[6]  += x * wb.z;  acc[7]  += x * wb.w;
            acc[8]  += x * wc.x;  acc[9]  += x * wc.y;  acc[10] += x * wc.z;  acc[11] += x * wc.w;
            acc[12] += x * wd.x;  acc[13] += x * wd.y;  acc[14] += x * wd.z;  acc[15] += x * wd.w;
        }
    }
    uint4 r0, r1;
    ((__half2*)&r0)[0] = __floats2half2_rn(acc[0],  acc[1]);
    ((__half2*)&r0)[1] = __floats2half2_rn(acc[2],  acc[3]);
    ((__half2*)&r0)[2] = __floats2half2_rn(acc[4],  acc[5]);
    ((__half2*)&r0)[3] = __floats2half2_rn(acc[6],  acc[7]);
    ((__half2*)&r1)[0] = __floats2half2_rn(acc[8],  acc[9]);
    ((__half2*)&r1)[1] = __floats2half2_rn(acc[10], acc[11]);
    ((__half2*)&r1)[2] = __floats2half2_rn(acc[12], acc[13]);
    ((__half2*)&r1)[3] = __floats2half2_rn(acc[14], acc[15]);
    uint4* op = reinterpret_cast<uint4*>(g_XW1h) + (size_t)row * 2;
    op[0] = r0;
    op[1] = r1;
}

// ---------------- edge gather helper: one packed member into acc -------------
#define EG_STEP(SRC, P, ACC, WSUM)                                             \
    {                                                                          \
        int _v; float _wv; unpack_vw((P), _v, _wv);                            \
        uint2 _r = __ldg(&(SRC)[(size_t)_v * 4 + c]);                          \
        float2 _f0 = __half22float2(*reinterpret_cast<__half2*>(&_r.x));       \
        float2 _f1 = __half22float2(*reinterpret_cast<__half2*>(&_r.y));       \
        (ACC).x += _wv * _f0.x; (ACC).y += _wv * _f0.y;                        \
        (ACC).z += _wv * _f1.x; (ACC).w += _wv * _f1.y;                        \
        (WSUM) += _wv;                                                         \
    }

// ---------------- edge gather 1: warp/edge, 8 groups x 4-lane, unroll x2 -----
__global__ void edge_gather1_kernel() {
    int warp = (blockIdx.x * blockDim.x + threadIdx.x) >> 5;
    int lane = threadIdx.x & 31;
    int g = lane >> 2, c = lane & 3;
    bool active = warp < N_EDGES;
    int e = active ? warp : 0;

    cudaGridDependencySynchronize();
    if (!active) return;

    int cnt = min(__ldg(&g_cnt_e[e]), PAD_E);
    const unsigned* buf = g_buf_e + (size_t)e * PAD_E;
    const uint2* xr = reinterpret_cast<const uint2*>(g_XW1h);
    float4 a0 = make_float4(0.f, 0.f, 0.f, 0.f), a1 = make_float4(0.f, 0.f, 0.f, 0.f);
    float s0 = 0.f, s1 = 0.f;
    int mb = 0;
    for (; mb + 16 <= cnt; mb += 16) {      // two independent member streams
        unsigned p0 = __ldg(&buf[mb + g]);
        unsigned p1 = __ldg(&buf[mb + 8 + g]);
        EG_STEP(xr, p0, a0, s0);
        EG_STEP(xr, p1, a1, s1);
    }
    for (; mb + 8 <= cnt; mb += 8) {
        unsigned p0 = __ldg(&buf[mb + g]);
        EG_STEP(xr, p0, a0, s0);
    }
    if (mb + g < cnt) {
        unsigned p0 = __ldg(&buf[mb + g]);
        EG_STEP(xr, p0, a1, s1);
    }
    float4 acc = make_float4(a0.x + a1.x, a0.y + a1.y, a0.z + a1.z, a0.w + a1.w);
    float wsum = s0 + s1;
#pragma unroll
    for (int st = 4; st < 32; st <<= 1) {
        acc.x += __shfl_xor_sync(0xFFFFFFFFu, acc.x, st);
        acc.y += __shfl_xor_sync(0xFFFFFFFFu, acc.y, st);
        acc.z += __shfl_xor_sync(0xFFFFFFFFu, acc.z, st);
        acc.w += __shfl_xor_sync(0xFFFFFFFFu, acc.w, st);
        wsum  += __shfl_xor_sync(0xFFFFFFFFu, wsum,  st);
    }
    if (g == 0) {
        float inv = __frcp_rn(fmaxf(wsum, 1e-6f));
        uint2 r;
        *reinterpret_cast<__half2*>(&r.x) = __floats2half2_rn(acc.x * inv, acc.y * inv);
        *reinterpret_cast<__half2*>(&r.y) = __floats2half2_rn(acc.z * inv, acc.w * inv);
        reinterpret_cast<uint2*>(g_e1h)[(size_t)e * 4 + c] = r;
    }
}

// ---------------- node gather helper ----------------
#define NG_STEP(SRC, E0, ACC)                                                  \
    {                                                                          \
        uint2 _r = __ldg(&(SRC)[(size_t)(E0) * 4 + c]);                        \
        float2 _f0 = __half22float2(*reinterpret_cast<__half2*>(&_r.x));       \
        float2 _f1 = __half22float2(*reinterpret_cast<__half2*>(&_r.y));       \
        (ACC).x += _f0.x; (ACC).y += _f0.y; (ACC).z += _f1.x; (ACC).w += _f1.y;\
    }

// ---------------- node gather 1: TWO nodes/warp, unroll x2 -------------------
__global__ void node_gather1_kernel(const float* __restrict__ b1) {
    int warp = (blockIdx.x * blockDim.x + threadIdx.x) >> 5;
    int lane = threadIdx.x & 31;
    int half = lane >> 4, l = lane & 15;
    int v = warp * 2 + half;
    int g = l >> 2, c = l & 3;
    float bias = __ldg(&b1[l]);

    cudaGridDependencySynchronize();
    if (v >= N_NODES) return;

    int cnt = min(__ldg(&g_cnt_v[v]), PAD_V);
    const int* buf = g_buf_v + (size_t)v * PAD_V;
    const uint2* er = reinterpret_cast<const uint2*>(g_e1h);
    float4 a0 = make_float4(0.f, 0.f, 0.f, 0.f), a1 = make_float4(0.f, 0.f, 0.f, 0.f);
    int mb = 0;
    for (; mb + 8 <= cnt; mb += 8) {
        int e0 = __ldg(&buf[mb + g]);
        int e1 = __ldg(&buf[mb + 4 + g]);
        NG_STEP(er, e0, a0);
        NG_STEP(er, e1, a1);
    }
    for (; mb + 4 <= cnt; mb += 4) {
        int e0 = __ldg(&buf[mb + g]);
        NG_STEP(er, e0, a0);
    }
    if (mb + g < cnt) {
        int e0 = __ldg(&buf[mb + g]);
        NG_STEP(er, e0, a1);
    }
    float4 acc = make_float4(a0.x + a1.x, a0.y + a1.y, a0.z + a1.z, a0.w + a1.w);
#pragma unroll
    for (int st = 4; st < 16; st <<= 1) {
        acc.x += __shfl_xor_sync(0xFFFFFFFFu, acc.x, st);
        acc.y += __shfl_xor_sync(0xFFFFFFFFu, acc.y, st);
        acc.z += __shfl_xor_sync(0xFFFFFFFFu, acc.z, st);
        acc.w += __shfl_xor_sync(0xFFFFFFFFu, acc.w, st);
    }
    if (g == 0) {
        float b0  = __shfl_sync(0xFFFFFFFFu, bias, (half << 4) + c * 4 + 0);
        float bb1 = __shfl_sync(0xFFFFFFFFu, bias, (half << 4) + c * 4 + 1);
        float b2v = __shfl_sync(0xFFFFFFFFu, bias, (half << 4) + c * 4 + 2);
        float b3  = __shfl_sync(0xFFFFFFFFu, bias, (half << 4) + c * 4 + 3);
        float invd = __frcp_rn(fmaxf((float)cnt, 1.f));
        float x0 = fmaxf(acc.x * invd + b0, 0.f);
        float x1 = fmaxf(acc.y * invd + bb1, 0.f);
        float x2 = fmaxf(acc.z * invd + b2v, 0.f);
        float x3 = fmaxf(acc.w * invd + b3, 0.f);
        uint2 r;
        *reinterpret_cast<__half2*>(&r.x) = __floats2half2_rn(x0, x1);
        *reinterpret_cast<__half2*>(&r.y) = __floats2half2_rn(x2, x3);
        reinterpret_cast<uint2*>(g_X2h)[(size_t)v * 4 + c] = r;
    }
}

// ---------------- edge gather 2: identical structure on X2, unroll x2 --------
__global__ void edge_gather2_kernel() {
    int warp = (blockIdx.x * blockDim.x + threadIdx.x) >> 5;
    int lane = threadIdx.x & 31;
    int g = lane >> 2, c = lane & 3;
    bool active = warp < N_EDGES;
    int e = active ? warp : 0;

    cudaGridDependencySynchronize();
    if (!active) return;

    int cnt = min(__ldg(&g_cnt_e[e]), PAD_E);
    const unsigned* buf = g_buf_e + (size_t)e * PAD_E;
    const uint2* xr = reinterpret_cast<const uint2*>(g_X2h);
    float4 a0 = make_float4(0.f, 0.f, 0.f, 0.f), a1 = make_float4(0.f, 0.f, 0.f, 0.f);
    float s0 = 0.f, s1 = 0.f;
    int mb = 0;
    for (; mb + 16 <= cnt; mb += 16) {
        unsigned p0 = __ldg(&buf[mb + g]);
        unsigned p1 = __ldg(&buf[mb + 8 + g]);
        EG_STEP(xr, p0, a0, s0);
        EG_STEP(xr, p1, a1, s1);
    }
    for (; mb + 8 <= cnt; mb += 8) {
        unsigned p0 = __ldg(&buf[mb + g]);
        EG_STEP(xr, p0, a0, s0);
    }
    if (mb + g < cnt) {
        unsigned p0 = __ldg(&buf[mb + g]);
        EG_STEP(xr, p0, a1, s1);
    }
    float4 acc = make_float4(a0.x + a1.x, a0.y + a1.y, a0.z + a1.z, a0.w + a1.w);
    float wsum = s0 + s1;
#pragma unroll
    for (int st = 4; st < 32; st <<= 1) {
        acc.x += __shfl_xor_sync(0xFFFFFFFFu, acc.x, st);
        acc.y += __shfl_xor_sync(0xFFFFFFFFu, acc.y, st);
        acc.z += __shfl_xor_sync(0xFFFFFFFFu, acc.z, st);
        acc.w += __shfl_xor_sync(0xFFFFFFFFu, acc.w, st);
        wsum  += __shfl_xor_sync(0xFFFFFFFFu, wsum,  st);
    }
    if (g == 0) {
        float inv = __frcp_rn(fmaxf(wsum, 1e-6f));
        uint2 r;
        *reinterpret_cast<__half2*>(&r.x) = __floats2half2_rn(acc.x * inv, acc.y * inv);
        *reinterpret_cast<__half2*>(&r.y) = __floats2half2_rn(acc.z * inv, acc.w * inv);
        reinterpret_cast<uint2*>(g_e2h)[(size_t)e * 4 + c] = r;
    }
}

// ---------------- node gather 2: TWO nodes/warp + W2 + b2 + log_softmax ------
__global__ void node_gather2_fin_kernel(float* __restrict__ out,
                                        const float* __restrict__ W2,
                                        const float* __restrict__ b2) {
    __shared__ float sW[D_HID * D_OUT];
    for (int i = threadIdx.x; i < D_HID * D_OUT; i += blockDim.x) sW[i] = W2[i];
    __syncthreads();

    cudaGridDependencySynchronize();

    int warp = (blockIdx.x * blockDim.x + threadIdx.x) >> 5;
    int lane = threadIdx.x & 31;
    int half = lane >> 4, l = lane & 15;
    int v = warp * 2 + half;
    if (v >= N_NODES) return;
    int cnt = min(__ldg(&g_cnt_v[v]), PAD_V);
    if (l == 0) g_cnt_v[v] = 0;
    if (l == 1 && v < N_EDGES) g_cnt_e[v] = 0;
    int g = l >> 2, c = l & 3;

    const int* buf = g_buf_v + (size_t)v * PAD_V;
    const uint2* er = reinterpret_cast<const uint2*>(g_e2h);
    float4 a0 = make_float4(0.f, 0.f, 0.f, 0.f), a1 = make_float4(0.f, 0.f, 0.f, 0.f);
    int mb = 0;
    for (; mb + 8 <= cnt; mb += 8) {
        int e0 = __ldg(&buf[mb + g]);
        int e1 = __ldg(&buf[mb + 4 + g]);
        NG_STEP(er, e0, a0);
        NG_STEP(er, e1, a1);
    }
    for (; mb + 4 <= cnt; mb += 4) {
        int e0 = __ldg(&buf[mb + g]);
        NG_STEP(er, e0, a0);
    }
    if (mb + g < cnt) {
        int e0 = __ldg(&buf[mb + g]);
        NG_STEP(er, e0, a1);
    }
    float4 acc = make_float4(a0.x + a1.x, a0.y + a1.y, a0.z + a1.z, a0.w + a1.w);
#pragma unroll
    for (int st = 4; st < 16; st <<= 1) {
        acc.x += __shfl_xor_sync(0xFFFFFFFFu, acc.x, st);
        acc.y += __shfl_xor_sync(0xFFFFFFFFu, acc.y, st);
        acc.z += __shfl_xor_sync(0xFFFFFFFFu, acc.z, st);
        acc.w += __shfl_xor_sync(0xFFFFFFFFu, acc.w, st);
    }
    float invd = __frcp_rn(fmaxf((float)cnt, 1.f));
    float4 vf;
    vf.x = acc.x * invd; vf.y = acc.y * invd; vf.z = acc.z * invd; vf.w = acc.w * invd;

    bool has3 = l < (D_OUT - 32);
    float o0 = 0.f, o1 = 0.f, o2 = 0.f;
#pragma unroll
    for (int k = 0; k < D_HID; k++) {
        int src = (half << 4) + (k >> 2);
        float comp = (k & 3) == 0 ? vf.x : (k & 3) == 1 ? vf.y : (k & 3) == 2 ? vf.z : vf.w;
        float xk = __shfl_sync(0xFFFFFFFFu, comp, src);
        o0 += xk * sW[k * D_OUT + l];
        o1 += xk * sW[k * D_OUT + 16 + l];
        if (has3) o2 += xk * sW[k * D_OUT + 32 + l];
    }
    float v0 = o0 + __ldg(&b2[l]);
    float v1 = o1 + __ldg(&b2[16 + l]);
    float v2 = has3 ? (o2 + __ldg(&b2[32 + l])) : -INFINITY;

    float mx = fmaxf(fmaxf(v0, v1), v2);
#pragma unroll
    for (int st = 8; st > 0; st >>= 1)
        mx = fmaxf(mx, __shfl_xor_sync(0xFFFFFFFFu, mx, st));
    float s = __expf(v0 - mx) + __expf(v1 - mx) + (has3 ? __expf(v2 - mx) : 0.f);
#pragma unroll
    for (int st = 8; st > 0; st >>= 1)
        s += __shfl_xor_sync(0xFFFFFFFFu, s, st);
    float lse = mx + __logf(s);

    float* r = out + (size_t)v * D_OUT;
    r[l] = v0 - lse;
    r[16 + l] = v1 - lse;
    if (has3) r[32 + l] = v2 - lse;
}

// ---------------- launch (PDL chain) ----------------
static inline void launch_pdl(void* fn, dim3 grid, dim3 block, void** args, bool pdl) {
    cudaLaunchConfig_t cfg = {};
    cfg.gridDim = grid;
    cfg.blockDim = block;
    cudaLaunchAttribute attr[1];
    if (pdl) {
        attr[0].id = cudaLaunchAttributeProgrammaticStreamSerialization;
        attr[0].val.programmaticStreamSerializationAllowed = 1;
        cfg.attrs = attr;
        cfg.numAttrs = 1;
    }
    cudaLaunchKernelExC(&cfg, fn, args);
}

extern "C" void kernel_launch(void* const* d_in, const int* in_sizes, int n_in,
                              void* d_out, int out_size) {
    const float* H   = (const float*)d_in[0];
    const float* w   = (const float*)d_in[1];
    const int*   ni  = (const int*)  d_in[2];
    const int*   ei  = (const int*)  d_in[3];
    const float* W1  = (const float*)d_in[4];
    const float* b1  = (const float*)d_in[5];
    const float* W2  = (const float*)d_in[6];
    const float* b2  = (const float*)d_in[7];
    float*       out = (float*)d_out;

    const int T = 256;
    auto blocks = [](long n, int t) { return (int)((n + t - 1) / t); };

    {
        void* args[] = {(void*)&H, (void*)&W1, (void*)&ni, (void*)&ei, (void*)&w};
        launch_pdl((void*)gemm1_fill_kernel, dim3(GEMM1_BLOCKS + FILL_BLOCKS), dim3(T), args, false);
    }
    {
        void* args[] = {};
        launch_pdl((void*)edge_gather1_kernel, dim3(blocks((long)N_EDGES * 32, T)), dim3(T), args, true);
    }
    {
        void* args[] = {(void*)&b1};
        launch_pdl((void*)node_gather1_kernel, dim3(blocks((long)N_NODES * 16, T)), dim3(T), args, true);
    }
    {
        void* args[] = {};
        launch_pdl((void*)edge_gather2_kernel, dim3(blocks((long)N_EDGES * 32, T)), dim3(T), args, true);
    }
    {
        void* args[] = {(void*)&out, (void*)&W2, (void*)&b2};
        launch_pdl((void*)node_gather2_fin_kernel, dim3(blocks((long)N_NODES * 16, T)), dim3(T), args, true);
    }
}

// round 14
// speedup vs baseline: 1.0190x; 1.0190x over previous
#include <cuda_runtime.h>
#include <cuda_bf16.h>
#include <cuda_fp16.h>
#include <math.h>

#define N_NODES 100000
#define N_EDGES 20000
#define N_INC   800000
#define D_IN    256
#define D_HID   16
#define D_OUT   40
#define PAD_E   128
#define PAD_V   64

// ---------------- scratch (device globals) ----------------
__device__ __half2 g_XW1h[(size_t)N_NODES * (D_HID / 2)]; // H@W1, fp16, 32B rows
__device__ __half2 g_e1h [(size_t)N_EDGES * (D_HID / 2)]; // e_feat1, fp16, 32B rows
__device__ __half2 g_X2h [(size_t)N_NODES * (D_HID / 2)]; // x=relu(...), fp16, 32B rows
__device__ __half2 g_e2h [(size_t)N_EDGES * (D_HID / 2)]; // e_feat2, fp16, 32B rows
__device__ int     g_cnt_e[N_EDGES];   // zero-init; re-zeroed by ng2 each call
__device__ int     g_cnt_v[N_NODES];   // zero-init; re-zeroed by ng2 each call
__device__ int2    g_buf_e[(size_t)N_EDGES * PAD_E];      // {node idx, w bits}
__device__ int     g_buf_v[(size_t)N_NODES * PAD_V];      // edge idx

// ---------------- GEMM1 + bucket fill (merged; disjoint block ranges) --------
#define GEMM1_BLOCKS ((N_NODES + 255) / 256)
#define FILL_BLOCKS  ((N_INC + 255) / 256)
__global__ void gemm1_fill_kernel(const float* __restrict__ H, const float* __restrict__ W1,
                                  const int* __restrict__ ni, const int* __restrict__ ei,
                                  const float* __restrict__ w) {
    if (blockIdx.x >= GEMM1_BLOCKS) {
        int i = (blockIdx.x - GEMM1_BLOCKS) * blockDim.x + threadIdx.x;
        if (i >= N_INC) return;
        int v = __ldg(&ni[i]);
        int e = __ldg(&ei[i]);
        float wv = __ldg(&w[v]);
        int se = atomicAdd(&g_cnt_e[e], 1);
        if (se < PAD_E) g_buf_e[(size_t)e * PAD_E + se] = make_int2(v, __float_as_int(wv));
        int sv = atomicAdd(&g_cnt_v[v], 1);
        if (sv < PAD_V) g_buf_v[(size_t)v * PAD_V + sv] = e;
        return;
    }
    __shared__ float sW[D_IN * D_HID];
    for (int i = threadIdx.x; i < D_IN * D_HID; i += blockDim.x) sW[i] = W1[i];
    __syncthreads();

    int row = blockIdx.x * blockDim.x + threadIdx.x;
    if (row >= N_NODES) return;

    // 8 packed f32x2 accumulators: acc2[j] covers output cols {2j, 2j+1}
    unsigned long long acc2[8];
#pragma unroll
    for (int j = 0; j < 8; j++)
        asm("mov.b64 %0, {%1, %1};" : "=l"(acc2[j]) : "f"(0.f));

    const float4* hp = reinterpret_cast<const float4*>(H + (size_t)row * D_IN);
#pragma unroll 4
    for (int k4 = 0; k4 < D_IN / 4; k4++) {
        float4 hv = __ldcs(&hp[k4]);
        float xs[4] = {hv.x, hv.y, hv.z, hv.w};
#pragma unroll
        for (int c = 0; c < 4; c++) {
            unsigned long long x2;
            asm("mov.b64 %0, {%1, %1};" : "=l"(x2) : "f"(xs[c]));
            const unsigned long long* w2 =
                reinterpret_cast<const unsigned long long*>(&sW[(k4 * 4 + c) * D_HID]);
#pragma unroll
            for (int j = 0; j < 8; j++) {
                unsigned long long wv = w2[j];     // LDS.64 (broadcast)
                asm("fma.rn.f32x2 %0, %1, %2, %0;" : "+l"(acc2[j]) : "l"(x2), "l"(wv));
            }
        }
    }
    // unpack 8 pairs -> 16 fp32 -> 8 half2 -> two uint4 stores
    float a[D_HID];
#pragma unroll
    for (int j = 0; j < 8; j++)
        asm("mov.b64 {%0, %1}, %2;" : "=f"(a[2 * j]), "=f"(a[2 * j + 1]) : "l"(acc2[j]));
    uint4 r0, r1;
    ((__half2*)&r0)[0] = __floats2half2_rn(a[0],  a[1]);
    ((__half2*)&r0)[1] = __floats2half2_rn(a[2],  a[3]);
    ((__half2*)&r0)[2] = __floats2half2_rn(a[4],  a[5]);
    ((__half2*)&r0)[3] = __floats2half2_rn(a[6],  a[7]);
    ((__half2*)&r1)[0] = __floats2half2_rn(a[8],  a[9]);
    ((__half2*)&r1)[1] = __floats2half2_rn(a[10], a[11]);
    ((__half2*)&r1)[2] = __floats2half2_rn(a[12], a[13]);
    ((__half2*)&r1)[3] = __floats2half2_rn(a[14], a[15]);
    uint4* op = reinterpret_cast<uint4*>(g_XW1h) + (size_t)row * 2;
    op[0] = r0;
    op[1] = r1;
}

// ---------------- edge gather 1: warp/edge, 8 groups x 4-lane uint2 ----------
__global__ void edge_gather1_kernel() {
    int warp = (blockIdx.x * blockDim.x + threadIdx.x) >> 5;
    int lane = threadIdx.x & 31;
    int g = lane >> 2, c = lane & 3;
    bool active = warp < N_EDGES;
    int e = active ? warp : 0;

    cudaGridDependencySynchronize();   // wait for gemm1_fill results
    if (!active) return;

    int cnt = min(__ldg(&g_cnt_e[e]), PAD_E);
    const int2* buf = g_buf_e + (size_t)e * PAD_E;
    const uint2* xr = reinterpret_cast<const uint2*>(g_XW1h);
    float4 acc = make_float4(0.f, 0.f, 0.f, 0.f);
    float wsum = 0.f;
    int mb = 0;
    for (; mb + 8 <= cnt; mb += 8) {
        int2 p = __ldg(&buf[mb + g]);
        float wv = __int_as_float(p.y);
        uint2 r = __ldg(&xr[(size_t)p.x * 4 + c]);
        float2 f0 = __half22float2(*reinterpret_cast<__half2*>(&r.x));
        float2 f1 = __half22float2(*reinterpret_cast<__half2*>(&r.y));
        acc.x += wv * f0.x; acc.y += wv * f0.y; acc.z += wv * f1.x; acc.w += wv * f1.y;
        wsum += wv;
    }
    if (mb + g < cnt) {
        int2 p = __ldg(&buf[mb + g]);
        float wv = __int_as_float(p.y);
        uint2 r = __ldg(&xr[(size_t)p.x * 4 + c]);
        float2 f0 = __half22float2(*reinterpret_cast<__half2*>(&r.x));
        float2 f1 = __half22float2(*reinterpret_cast<__half2*>(&r.y));
        acc.x += wv * f0.x; acc.y += wv * f0.y; acc.z += wv * f1.x; acc.w += wv * f1.y;
        wsum += wv;
    }
#pragma unroll
    for (int st = 4; st < 32; st <<= 1) {
        acc.x += __shfl_xor_sync(0xFFFFFFFFu, acc.x, st);
        acc.y += __shfl_xor_sync(0xFFFFFFFFu, acc.y, st);
        acc.z += __shfl_xor_sync(0xFFFFFFFFu, acc.z, st);
        acc.w += __shfl_xor_sync(0xFFFFFFFFu, acc.w, st);
        wsum  += __shfl_xor_sync(0xFFFFFFFFu, wsum,  st);
    }
    if (g == 0) {
        float inv = __frcp_rn(fmaxf(wsum, 1e-6f));
        uint2 r;
        *reinterpret_cast<__half2*>(&r.x) = __floats2half2_rn(acc.x * inv, acc.y * inv);
        *reinterpret_cast<__half2*>(&r.y) = __floats2half2_rn(acc.z * inv, acc.w * inv);
        reinterpret_cast<uint2*>(g_e1h)[(size_t)e * 4 + c] = r;
    }
}

// ---------------- node gather 1: TWO nodes/warp; x=relu(mean+b1) -> fp16 -----
__global__ void node_gather1_kernel(const float* __restrict__ b1) {
    int warp = (blockIdx.x * blockDim.x + threadIdx.x) >> 5;
    int lane = threadIdx.x & 31;
    int half = lane >> 4, l = lane & 15;
    int v = warp * 2 + half;
    int g = l >> 2, c = l & 3;
    float bias = __ldg(&b1[l]);     // harness input: safe pre-sync

    cudaGridDependencySynchronize();   // wait for edge_gather1 results
    if (v >= N_NODES) return;

    int cnt = min(__ldg(&g_cnt_v[v]), PAD_V);
    const int* buf = g_buf_v + (size_t)v * PAD_V;
    const uint2* er = reinterpret_cast<const uint2*>(g_e1h);
    float4 acc = make_float4(0.f, 0.f, 0.f, 0.f);
    int mb = 0;
    for (; mb + 4 <= cnt; mb += 4) {
        int e0 = __ldg(&buf[mb + g]);
        uint2 r = __ldg(&er[(size_t)e0 * 4 + c]);
        float2 f0 = __half22float2(*reinterpret_cast<__half2*>(&r.x));
        float2 f1 = __half22float2(*reinterpret_cast<__half2*>(&r.y));
        acc.x += f0.x; acc.y += f0.y; acc.z += f1.x; acc.w += f1.y;
    }
    if (mb + g < cnt) {
        int e0 = __ldg(&buf[mb + g]);
        uint2 r = __ldg(&er[(size_t)e0 * 4 + c]);
        float2 f0 = __half22float2(*reinterpret_cast<__half2*>(&r.x));
        float2 f1 = __half22float2(*reinterpret_cast<__half2*>(&r.y));
        acc.x += f0.x; acc.y += f0.y; acc.z += f1.x; acc.w += f1.y;
    }
#pragma unroll
    for (int st = 4; st < 16; st <<= 1) {
        acc.x += __shfl_xor_sync(0xFFFFFFFFu, acc.x, st);
        acc.y += __shfl_xor_sync(0xFFFFFFFFu, acc.y, st);
        acc.z += __shfl_xor_sync(0xFFFFFFFFu, acc.z, st);
        acc.w += __shfl_xor_sync(0xFFFFFFFFu, acc.w, st);
    }
    if (g == 0) {
        float b0  = __shfl_sync(0xFFFFFFFFu, bias, (half << 4) + c * 4 + 0);
        float bb1 = __shfl_sync(0xFFFFFFFFu, bias, (half << 4) + c * 4 + 1);
        float b2v = __shfl_sync(0xFFFFFFFFu, bias, (half << 4) + c * 4 + 2);
        float b3  = __shfl_sync(0xFFFFFFFFu, bias, (half << 4) + c * 4 + 3);
        float invd = __frcp_rn(fmaxf((float)cnt, 1.f));
        float x0 = fmaxf(acc.x * invd + b0, 0.f);
        float x1 = fmaxf(acc.y * invd + bb1, 0.f);
        float x2 = fmaxf(acc.z * invd + b2v, 0.f);
        float x3 = fmaxf(acc.w * invd + b3, 0.f);
        uint2 r;
        *reinterpret_cast<__half2*>(&r.x) = __floats2half2_rn(x0, x1);
        *reinterpret_cast<__half2*>(&r.y) = __floats2half2_rn(x2, x3);
        reinterpret_cast<uint2*>(g_X2h)[(size_t)v * 4 + c] = r;
    }
}

// ---------------- edge gather 2: identical structure on X2 -------------------
__global__ void edge_gather2_kernel() {
    int warp = (blockIdx.x * blockDim.x + threadIdx.x) >> 5;
    int lane = threadIdx.x & 31;
    int g = lane >> 2, c = lane & 3;
    bool active = warp < N_EDGES;
    int e = active ? warp : 0;

    cudaGridDependencySynchronize();   // wait for node_gather1 results
    if (!active) return;

    int cnt = min(__ldg(&g_cnt_e[e]), PAD_E);
    const int2* buf = g_buf_e + (size_t)e * PAD_E;
    const uint2* xr = reinterpret_cast<const uint2*>(g_X2h);
    float4 acc = make_float4(0.f, 0.f, 0.f, 0.f);
    float wsum = 0.f;
    int mb = 0;
    for (; mb + 8 <= cnt; mb += 8) {
        int2 p = __ldg(&buf[mb + g]);
        float wv = __int_as_float(p.y);
        uint2 r = __ldg(&xr[(size_t)p.x * 4 + c]);
        float2 f0 = __half22float2(*reinterpret_cast<__half2*>(&r.x));
        float2 f1 = __half22float2(*reinterpret_cast<__half2*>(&r.y));
        acc.x += wv * f0.x; acc.y += wv * f0.y; acc.z += wv * f1.x; acc.w += wv * f1.y;
        wsum += wv;
    }
    if (mb + g < cnt) {
        int2 p = __ldg(&buf[mb + g]);
        float wv = __int_as_float(p.y);
        uint2 r = __ldg(&xr[(size_t)p.x * 4 + c]);
        float2 f0 = __half22float2(*reinterpret_cast<__half2*>(&r.x));
        float2 f1 = __half22float2(*reinterpret_cast<__half2*>(&r.y));
        acc.x += wv * f0.x; acc.y += wv * f0.y; acc.z += wv * f1.x; acc.w += wv * f1.y;
        wsum += wv;
    }
#pragma unroll
    for (int st = 4; st < 32; st <<= 1) {
        acc.x += __shfl_xor_sync(0xFFFFFFFFu, acc.x, st);
        acc.y += __shfl_xor_sync(0xFFFFFFFFu, acc.y, st);
        acc.z += __shfl_xor_sync(0xFFFFFFFFu, acc.z, st);
        acc.w += __shfl_xor_sync(0xFFFFFFFFu, acc.w, st);
        wsum  += __shfl_xor_sync(0xFFFFFFFFu, wsum,  st);
    }
    if (g == 0) {
        float inv = __frcp_rn(fmaxf(wsum, 1e-6f));
        uint2 r;
        *reinterpret_cast<__half2*>(&r.x) = __floats2half2_rn(acc.x * inv, acc.y * inv);
        *reinterpret_cast<__half2*>(&r.y) = __floats2half2_rn(acc.z * inv, acc.w * inv);
        reinterpret_cast<uint2*>(g_e2h)[(size_t)e * 4 + c] = r;
    }
}

// ---------------- node gather 2: TWO nodes/warp + W2 + b2 + log_softmax ------
__global__ void node_gather2_fin_kernel(float* __restrict__ out,
                                        const float* __restrict__ W2,
                                        const float* __restrict__ b2) {
    __shared__ float sW[D_HID * D_OUT];
    for (int i = threadIdx.x; i < D_HID * D_OUT; i += blockDim.x) sW[i] = W2[i];
    __syncthreads();

    cudaGridDependencySynchronize();   // wait for edge_gather2 results

    int warp = (blockIdx.x * blockDim.x + threadIdx.x) >> 5;
    int lane = threadIdx.x & 31;
    int half = lane >> 4, l = lane & 15;
    int v = warp * 2 + half;
    if (v >= N_NODES) return;
    int cnt = min(__ldg(&g_cnt_v[v]), PAD_V);
    if (l == 0) g_cnt_v[v] = 0;                    // self-clean for next call
    if (l == 1 && v < N_EDGES) g_cnt_e[v] = 0;
    int g = l >> 2, c = l & 3;

    const int* buf = g_buf_v + (size_t)v * PAD_V;
    const uint2* er = reinterpret_cast<const uint2*>(g_e2h);
    float4 acc = make_float4(0.f, 0.f, 0.f, 0.f);
    int mb = 0;
    for (; mb + 4 <= cnt; mb += 4) {
        int e0 = __ldg(&buf[mb + g]);
        uint2 r = __ldg(&er[(size_t)e0 * 4 + c]);
        float2 f0 = __half22float2(*reinterpret_cast<__half2*>(&r.x));
        float2 f1 = __half22float2(*reinterpret_cast<__half2*>(&r.y));
        acc.x += f0.x; acc.y += f0.y; acc.z += f1.x; acc.w += f1.y;
    }
    if (mb + g < cnt) {
        int e0 = __ldg(&buf[mb + g]);
        uint2 r = __ldg(&er[(size_t)e0 * 4 + c]);
        float2 f0 = __half22float2(*reinterpret_cast<__half2*>(&r.x));
        float2 f1 = __half22float2(*reinterpret_cast<__half2*>(&r.y));
        acc.x += f0.x; acc.y += f0.y; acc.z += f1.x; acc.w += f1.y;
    }
#pragma unroll
    for (int st = 4; st < 16; st <<= 1) {
        acc.x += __shfl_xor_sync(0xFFFFFFFFu, acc.x, st);
        acc.y += __shfl_xor_sync(0xFFFFFFFFu, acc.y, st);
        acc.z += __shfl_xor_sync(0xFFFFFFFFu, acc.z, st);
        acc.w += __shfl_xor_sync(0xFFFFFFFFu, acc.w, st);
    }
    float invd = __frcp_rn(fmaxf((float)cnt, 1.f));
    float4 vf;
    vf.x = acc.x * invd; vf.y = acc.y * invd; vf.z = acc.z * invd; vf.w = acc.w * invd;

    bool has3 = l < (D_OUT - 32);
    float o0 = 0.f, o1 = 0.f, o2 = 0.f;
#pragma unroll
    for (int k = 0; k < D_HID; k++) {
        int src = (half << 4) + (k >> 2);
        float comp = (k & 3) == 0 ? vf.x : (k & 3) == 1 ? vf.y : (k & 3) == 2 ? vf.z : vf.w;
        float xk = __shfl_sync(0xFFFFFFFFu, comp, src);
        o0 += xk * sW[k * D_OUT + l];
        o1 += xk * sW[k * D_OUT + 16 + l];
        if (has3) o2 += xk * sW[k * D_OUT + 32 + l];
    }
    float v0 = o0 + __ldg(&b2[l]);
    float v1 = o1 + __ldg(&b2[16 + l]);
    float v2 = has3 ? (o2 + __ldg(&b2[32 + l])) : -INFINITY;

    float mx = fmaxf(fmaxf(v0, v1), v2);
#pragma unroll
    for (int st = 8; st > 0; st >>= 1)
        mx = fmaxf(mx, __shfl_xor_sync(0xFFFFFFFFu, mx, st));
    float s = __expf(v0 - mx) + __expf(v1 - mx) + (has3 ? __expf(v2 - mx) : 0.f);
#pragma unroll
    for (int st = 8; st > 0; st >>= 1)
        s += __shfl_xor_sync(0xFFFFFFFFu, s, st);
    float lse = mx + __logf(s);

    float* r = out + (size_t)v * D_OUT;
    r[l] = v0 - lse;
    r[16 + l] = v1 - lse;
    if (has3) r[32 + l] = v2 - lse;
}

// ---------------- launch (PDL chain) ----------------
static inline void launch_pdl(void* fn, dim3 grid, dim3 block, void** args, bool pdl) {
    cudaLaunchConfig_t cfg = {};
    cfg.gridDim = grid;
    cfg.blockDim = block;
    cudaLaunchAttribute attr[1];
    if (pdl) {
        attr[0].id = cudaLaunchAttributeProgrammaticStreamSerialization;
        attr[0].val.programmaticStreamSerializationAllowed = 1;
        cfg.attrs = attr;
        cfg.numAttrs = 1;
    }
    cudaLaunchKernelExC(&cfg, fn, args);
}

extern "C" void kernel_launch(void* const* d_in, const int* in_sizes, int n_in,
                              void* d_out, int out_size) {
    const float* H   = (const float*)d_in[0];
    const float* w   = (const float*)d_in[1];
    const int*   ni  = (const int*)  d_in[2];
    const int*   ei  = (const int*)  d_in[3];
    const float* W1  = (const float*)d_in[4];
    const float* b1  = (const float*)d_in[5];
    const float* W2  = (const float*)d_in[6];
    const float* b2  = (const float*)d_in[7];
    float*       out = (float*)d_out;

    const int T = 256;
    auto blocks = [](long n, int t) { return (int)((n + t - 1) / t); };

    {
        void* args[] = {(void*)&H, (void*)&W1, (void*)&ni, (void*)&ei, (void*)&w};
        launch_pdl((void*)gemm1_fill_kernel, dim3(GEMM1_BLOCKS + FILL_BLOCKS), dim3(T), args, false);
    }
    {
        void* args[] = {};
        launch_pdl((void*)edge_gather1_kernel, dim3(blocks((long)N_EDGES * 32, T)), dim3(T), args, true);
    }
    {
        void* args[] = {(void*)&b1};
        launch_pdl((void*)node_gather1_kernel, dim3(blocks((long)N_NODES * 16, T)), dim3(T), args, true);
    }
    {
        void* args[] = {};
        launch_pdl((void*)edge_gather2_kernel, dim3(blocks((long)N_EDGES * 32, T)), dim3(T), args, true);
    }
    {
        void* args[] = {(void*)&out, (void*)&W2, (void*)&b2};
        launch_pdl((void*)node_gather2_fin_kernel, dim3(blocks((long)N_NODES * 16, T)), dim3(T), args, true);
    }
}